// round 16
// baseline (speedup 1.0000x reference)
#include <cuda_runtime.h>
#include <cuda_fp16.h>
#include <math.h>
#include <stdint.h>

// Problem constants
#define Bsz 4
#define Cc  64
#define Nn  4096
#define HIDD 256
#define EPSBN 1e-5f
#define LOG2E 1.44269504088896340736f

// ---------------- scratch (__device__ globals; no allocation) ----------------
__device__ float  gFl [Bsz*Cc*Nn];
__device__ __half gQ  [Bsz*Nn*64];     // q~ = M^T x, token-major
__device__ __half gK  [Bsz*Nn*64];     // k = x, token-major fp16
__device__ __half gVT [Bsz*Cc*Nn];     // v~ = (Wproj Wv) x, out-channel-major
__device__ float  gY  [Bsz*Cc*Nn];
__device__ float  gBNsum[2*Cc];

__device__ __half gMh  [4096];
__device__ __half gWpvh[4096];
__device__ __half gW1h [HIDD*Cc];
__device__ __half gW2h [Cc*HIDD];

// ---------------- helpers ----------------
__device__ __forceinline__ void mma_f16(float* c, const uint32_t* a, uint32_t b0, uint32_t b1) {
    asm volatile(
        "mma.sync.aligned.m16n8k16.row.col.f32.f16.f16.f32 "
        "{%0,%1,%2,%3}, {%4,%5,%6,%7}, {%8,%9}, {%0,%1,%2,%3};"
        : "+f"(c[0]), "+f"(c[1]), "+f"(c[2]), "+f"(c[3])
        : "r"(a[0]), "r"(a[1]), "r"(a[2]), "r"(a[3]), "r"(b0), "r"(b1));
}
__device__ __forceinline__ void ldsm_x4(uint32_t* r, const __half* p) {
    uint32_t addr = (uint32_t)__cvta_generic_to_shared(p);
    asm volatile("ldmatrix.sync.aligned.m8n8.x4.shared.b16 {%0,%1,%2,%3}, [%4];"
        : "=r"(r[0]), "=r"(r[1]), "=r"(r[2]), "=r"(r[3]) : "r"(addr));
}
__device__ __forceinline__ uint32_t pack2(float x, float y) {
    __half2 h = __floats2half2_rn(x, y);
    return *(uint32_t*)&h;
}
__device__ __forceinline__ uint32_t h2ex2(float x, float y) {
    uint32_t p = pack2(x, y), r;
    asm("ex2.approx.f16x2 %0, %1;" : "=r"(r) : "r"(p));
    return r;
}
__device__ __forceinline__ __half2 u2h2(uint32_t u) { return *(__half2*)&u; }
__device__ __forceinline__ void cp16(void* s, const void* g) {
    uint32_t sa = (uint32_t)__cvta_generic_to_shared(s);
    asm volatile("cp.async.cg.shared.global [%0], [%1], 16;" :: "r"(sa), "l"(g));
}

// ---------------- K0: prep ----------------
__global__ void __launch_bounds__(256) prep_kernel(
    const float* __restrict__ Wq1, const float* __restrict__ Wk1,
    const float* __restrict__ Wq2, const float* __restrict__ Wk2,
    const float* __restrict__ Wv,  const float* __restrict__ Wproj,
    const float* __restrict__ W1,  const float* __restrict__ W2,
    const float* __restrict__ lam_p)
{
    if (blockIdx.x < 64) {
        __shared__ float red[3][64];
        int j  = blockIdx.x;
        int c  = threadIdx.x & 63;
        int sl = threadIdx.x >> 6;
        float lam = __ldg(lam_p);
        float acc = 0.f;
        #pragma unroll
        for (int i = 0; i < 16; i++) {
            int d = sl*16 + i;
            acc = fmaf(__ldg(&Wk1[d*64 + j]), __ldg(&Wq1[d*64 + c]), acc);
            acc = fmaf(-lam*__ldg(&Wk2[d*64 + j]), __ldg(&Wq2[d*64 + c]), acc);
        }
        if (sl > 0) red[sl - 1][c] = acc;
        __syncthreads();
        if (sl == 0) {
            float s = acc + red[0][c] + red[1][c] + red[2][c];
            gMh[j*64 + c] = __float2half(s * 0.125f * LOG2E);
        }
    } else if (blockIdx.x < 128) {
        __shared__ float red[3][64];
        int j  = blockIdx.x - 64;
        int c  = threadIdx.x & 63;
        int sl = threadIdx.x >> 6;
        float acc = 0.f;
        #pragma unroll
        for (int i = 0; i < 16; i++) {
            int d = sl*16 + i;
            acc = fmaf(__ldg(&Wproj[j*64 + d]), __ldg(&Wv[d*64 + c]), acc);
        }
        if (sl > 0) red[sl - 1][c] = acc;
        __syncthreads();
        if (sl == 0) {
            float s = acc + red[0][c] + red[1][c] + red[2][c];
            gWpvh[j*64 + c] = __float2half(s);
        }
    } else {
        int bb = blockIdx.x - 128;
        if (bb == 0 && threadIdx.x < 128) gBNsum[threadIdx.x] = 0.f;
        int base = bb*512 + threadIdx.x;
        #pragma unroll
        for (int r = 0; r < 2; r++) {
            int i = base + r*256;
            if (i < 16384)       gW1h[i]         = __float2half(__ldg(&W1[i]));
            else                 gW2h[i - 16384] = __float2half(__ldg(&W2[i - 16384]));
        }
    }
}

// ---------------- K1: fused add + q~ / v~ projections + k copy ----------------
#define XS_LD 72
#define WS_LD 72
#define VTS_LD 136
#define PROJ_SMEM_HALFS (128*XS_LD + 128*WS_LD)

__global__ void __launch_bounds__(256) proj_kernel(
    const float* __restrict__ Fs, const float* __restrict__ Ff)
{
    extern __shared__ __half shp[];
    __half* xs = shp;
    __half* ws = shp + 128*XS_LD;

    int b  = blockIdx.y;
    int n0 = blockIdx.x << 7;
    int t  = threadIdx.x;
    int w = t >> 5, lane = t & 31, g = lane >> 2, t4 = lane & 3;
    int lrow = lane & 7, lcol = (lane >> 3) * 8;

    for (int idx = t; idx < 8192; idx += 256) {
        int c = idx >> 7, n = idx & 127;
        size_t gi = (size_t)((b<<6) + c)*Nn + n0 + n;
        float v = Fs[gi] + Ff[gi];
        gFl[gi] = v;
        xs[n*XS_LD + c] = __float2half(v);
    }
    for (int idx = t; idx < 512; idx += 256) {
        int r = idx >> 3, ch = idx & 7;
        *(uint4*)&ws[r*WS_LD + ch*8] = ((const uint4*)gMh)[r*8 + ch];
    }
    for (int idx = t; idx < 512; idx += 256) {
        int r = idx >> 3, ch = idx & 7;
        *(uint4*)&ws[(64 + r)*WS_LD + ch*8] = ((const uint4*)gWpvh)[r*8 + ch];
    }
    __syncthreads();

    for (int idx = t; idx < 1024; idx += 256) {
        int r = idx >> 3, ch = idx & 7;
        ((uint4*)&gK[(size_t)(b*Nn + n0 + r)*64])[ch] = *(uint4*)&xs[r*XS_LD + ch*8];
    }

    int row0 = w*16 + g;

    uint32_t xa[4][4];
    #pragma unroll
    for (int ks = 0; ks < 4; ks++) {
        xa[ks][0] = *(uint32_t*)&xs[ row0     *XS_LD + 16*ks + 2*t4];
        xa[ks][1] = *(uint32_t*)&xs[(row0 + 8)*XS_LD + 16*ks + 2*t4];
        xa[ks][2] = *(uint32_t*)&xs[ row0     *XS_LD + 16*ks + 2*t4 + 8];
        xa[ks][3] = *(uint32_t*)&xs[(row0 + 8)*XS_LD + 16*ks + 2*t4 + 8];
    }

    for (int m = 0; m < 2; m++) {
        float acc[8][4];
        #pragma unroll
        for (int nt = 0; nt < 8; nt++)
            acc[nt][0] = acc[nt][1] = acc[nt][2] = acc[nt][3] = 0.f;

        #pragma unroll
        for (int nt = 0; nt < 8; nt++) {
            const __half* wb = ws + (m*64 + nt*8 + lrow)*WS_LD + lcol;
            #pragma unroll
            for (int ks2 = 0; ks2 < 2; ks2++) {
                uint32_t bb[4];
                ldsm_x4(bb, wb + 32*ks2);
                mma_f16(acc[nt], xa[2*ks2],     bb[0], bb[1]);
                mma_f16(acc[nt], xa[2*ks2 + 1], bb[2], bb[3]);
            }
        }

        if (m == 1) {
            __syncthreads();
            __half* vts = xs;              // [64 d][VTS_LD]
            #pragma unroll
            for (int nt = 0; nt < 8; nt++) {
                int d0 = nt*8 + 2*t4;
                vts[ d0     *VTS_LD + row0    ] = __float2half(acc[nt][0]);
                vts[(d0 + 1)*VTS_LD + row0    ] = __float2half(acc[nt][1]);
                vts[ d0     *VTS_LD + row0 + 8] = __float2half(acc[nt][2]);
                vts[(d0 + 1)*VTS_LD + row0 + 8] = __float2half(acc[nt][3]);
            }
            __syncthreads();
            for (int idx = t; idx < 1024; idx += 256) {
                int d = idx >> 4, ch = idx & 15;
                ((uint4*)&gVT[(size_t)((b<<6) + d)*Nn + n0])[ch] = *(uint4*)&vts[d*VTS_LD + ch*8];
            }
        } else {
            #pragma unroll
            for (int nt = 0; nt < 8; nt++) {
                *(uint32_t*)&gQ[(size_t)(b*Nn + n0 + row0    )*64 + nt*8 + 2*t4]
                    = pack2(acc[nt][0], acc[nt][1]);
                *(uint32_t*)&gQ[(size_t)(b*Nn + n0 + row0 + 8)*64 + nt*8 + 2*t4]
                    = pack2(acc[nt][2], acc[nt][3]);
            }
        }
    }
}

// ---------------- K2: flash (work-stealing spare warps) + FFN + BN partials ----------------
#define KTILE 128
#define KS_LD 72
#define VT_LD 136
#define W1_LD 72
#define W2_LD 264
#define QS_LD 72
#define YS_LD 132
#define KBUF_B (KTILE*KS_LD*2)        // 18432
#define VBUF_B (64*VT_LD*2)           // 17408
#define KB0 0
#define KB1 KBUF_B
#define VB0 (2*KBUF_B)
#define VB1 (2*KBUF_B + VBUF_B)
#define W1o (2*KBUF_B + 2*VBUF_B)                 // 71680
#define W2o (W1o + HIDD*W1_LD*2)                  // 108544
#define Qo  (W2o + 64*W2_LD*2)                    // 142336
#define SLOTo (Qo + 128*QS_LD*2)                  // 160768
#define FLASH_SMEM_BYTES (SLOTo + 7*32*34*4)      // 191232

#define LOAD_QA(qsm, r0, r1) do {                                        \
    qa[0][0] = *(uint32_t*)&(qsm)[(r0)*QS_LD +  0 + 2*t4];               \
    qa[0][1] = *(uint32_t*)&(qsm)[(r1)*QS_LD +  0 + 2*t4];               \
    qa[0][2] = *(uint32_t*)&(qsm)[(r0)*QS_LD +  8 + 2*t4];               \
    qa[0][3] = *(uint32_t*)&(qsm)[(r1)*QS_LD +  8 + 2*t4];               \
    qa[1][0] = *(uint32_t*)&(qsm)[(r0)*QS_LD + 16 + 2*t4];               \
    qa[1][1] = *(uint32_t*)&(qsm)[(r1)*QS_LD + 16 + 2*t4];               \
    qa[1][2] = *(uint32_t*)&(qsm)[(r0)*QS_LD + 24 + 2*t4];               \
    qa[1][3] = *(uint32_t*)&(qsm)[(r1)*QS_LD + 24 + 2*t4];               \
    qa[2][0] = *(uint32_t*)&(qsm)[(r0)*QS_LD + 32 + 2*t4];               \
    qa[2][1] = *(uint32_t*)&(qsm)[(r1)*QS_LD + 32 + 2*t4];               \
    qa[2][2] = *(uint32_t*)&(qsm)[(r0)*QS_LD + 40 + 2*t4];               \
    qa[2][3] = *(uint32_t*)&(qsm)[(r1)*QS_LD + 40 + 2*t4];               \
    qa[3][0] = *(uint32_t*)&(qsm)[(r0)*QS_LD + 48 + 2*t4];               \
    qa[3][1] = *(uint32_t*)&(qsm)[(r1)*QS_LD + 48 + 2*t4];               \
    qa[3][2] = *(uint32_t*)&(qsm)[(r0)*QS_LD + 56 + 2*t4];               \
    qa[3][3] = *(uint32_t*)&(qsm)[(r1)*QS_LD + 56 + 2*t4];               \
} while (0)

__global__ void __launch_bounds__(256) flash_kernel()
{
    extern __shared__ char smem[];
    __half* w1s = (__half*)(smem + W1o);
    __half* w2s = (__half*)(smem + W2o);
    __half* qsm = (__half*)(smem + Qo);
    float*  slots = (float*)(smem + SLOTo);

    int bx = blockIdx.x;
    int b  = blockIdx.y;
    int nq   = (bx < 34) ? 112 : 96;
    int q0   = (bx < 34) ? bx*112 : 3808 + (bx - 34)*96;
    int nwq  = nq >> 4;               // 7 or 6

    int t  = threadIdx.x;
    int w = t >> 5, lane = t & 31, g = lane >> 2, t4 = lane & 3;
    bool act = (w < nwq);
    int row0 = act ? (w*16 + g) : g;
    int row1 = row0 + 8;
    int lrow = lane & 7, lcol = (lane >> 3) * 8;

    // stage FFN weights
    for (int idx = t; idx < 2048; idx += 256) {
        int e = idx >> 3, ch = idx & 7;
        *(uint4*)&w1s[e*W1_LD + ch*8] = ((const uint4*)gW1h)[e*8 + ch];
    }
    for (int idx = t; idx < 2048; idx += 256) {
        int c = idx >> 5, ch = idx & 31;
        *(uint4*)&w2s[c*W2_LD + ch*8] = ((const uint4*)gW2h)[c*32 + ch];
    }
    // stage Q into dedicated persistent region
    const uint4* Qg = (const uint4*)(gQ + (size_t)(b*Nn + q0)*64);
    for (int idx = t; idx < nq*8; idx += 256) {
        int r = idx >> 3, ch = idx & 7;
        *(uint4*)&qsm[r*QS_LD + ch*8] = Qg[r*8 + ch];
    }
    __syncthreads();

    uint32_t qa[4][4];
    if (act) LOAD_QA(qsm, row0, row1);

    float oc[8][4];
    #pragma unroll
    for (int nt = 0; nt < 8; nt++)
        oc[nt][0] = oc[nt][1] = oc[nt][2] = oc[nt][3] = 0.f;
    float l0 = 0.f, l1 = 0.f;

    // work-steal schedule
    bool spare = !act;
    int skipbase = (nwq == 7) ? (w << 2) : ((w % 3) << 3);
    int skipend  = skipbase + ((nwq == 7) ? 4 : 8);
    int sprev = -1;

    const uint4* Kg = (const uint4*)(gK  + (size_t)b*Nn*64);
    const uint4* Vg = (const uint4*)(gVT + (size_t)b*64*Nn);

    {   // prefetch tile 0
        __half* kd = (__half*)(smem + KB0);
        __half* vd = (__half*)(smem + VB0);
        for (int idx = t; idx < 1024; idx += 256) {
            int r = idx >> 3, ch = idx & 7;
            cp16(&kd[r*KS_LD + ch*8], &Kg[r*8 + ch]);
        }
        for (int idx = t; idx < 1024; idx += 256) {
            int d = idx >> 4, ch = idx & 15;
            cp16(&vd[d*VT_LD + ch*8], &Vg[d*512 + ch]);
        }
        asm volatile("cp.async.commit_group;");
    }

    for (int kt = 0; kt < Nn/KTILE; kt++) {
        __half* kc = (__half*)(smem + (kt & 1 ? KB1 : KB0));
        __half* vc = (__half*)(smem + (kt & 1 ? VB1 : VB0));

        if (kt + 1 < Nn/KTILE) {
            __half* kd = (__half*)(smem + ((kt + 1) & 1 ? KB1 : KB0));
            __half* vd = (__half*)(smem + ((kt + 1) & 1 ? VB1 : VB0));
            int kt0 = (kt + 1) * KTILE;
            for (int idx = t; idx < 1024; idx += 256) {
                int r = idx >> 3, ch = idx & 7;
                cp16(&kd[r*KS_LD + ch*8], &Kg[(kt0 + r)*8 + ch]);
            }
            for (int idx = t; idx < 1024; idx += 256) {
                int d = idx >> 4, ch = idx & 15;
                cp16(&vd[d*VT_LD + ch*8], &Vg[d*512 + (kt0 >> 3) + ch]);
            }
            asm volatile("cp.async.commit_group;");
            asm volatile("cp.async.wait_group 1;");
        } else {
            asm volatile("cp.async.wait_group 0;");
        }
        __syncthreads();

        // which row-tile does this warp cover at this kt? (-1 = idle)
        int cur;
        if (!spare) {
            cur = (kt >= skipbase && kt < skipend) ? -1 : w;
        } else if (nwq == 7) {
            cur = (kt < 28) ? (kt >> 2) : -1;
        } else {
            cur = (w == 6) ? ((kt < 24) ? (kt >> 3) : -1)
                           : ((kt < 24) ? 3 + (kt >> 3) : -1);
        }
        if (spare && cur != sprev) {
            if (sprev >= 0) {
                float* sp = slots + (size_t)(sprev*32 + lane)*34;
                #pragma unroll
                for (int nt = 0; nt < 8; nt++)
                    #pragma unroll
                    for (int j = 0; j < 4; j++) sp[nt*4 + j] = oc[nt][j];
                sp[32] = l0; sp[33] = l1;
                #pragma unroll
                for (int nt = 0; nt < 8; nt++)
                    oc[nt][0] = oc[nt][1] = oc[nt][2] = oc[nt][3] = 0.f;
                l0 = 0.f; l1 = 0.f;
            }
            if (cur >= 0) {
                int r0 = cur*16 + g;
                LOAD_QA(qsm, r0, r0 + 8);
            }
            sprev = cur;
        }

        if (cur >= 0) {
            // pipelined halves (unchanged compute body)
            float sc0[8][4];
            #pragma unroll
            for (int nt = 0; nt < 8; nt++) {
                sc0[nt][0] = sc0[nt][1] = sc0[nt][2] = sc0[nt][3] = 0.f;
                const __half* kb = &kc[(nt*8 + lrow)*KS_LD + lcol];
                #pragma unroll
                for (int ks2 = 0; ks2 < 2; ks2++) {
                    uint32_t bb[4];
                    ldsm_x4(bb, kb + 32*ks2);
                    mma_f16(sc0[nt], qa[2*ks2],     bb[0], bb[1]);
                    mma_f16(sc0[nt], qa[2*ks2 + 1], bb[2], bb[3]);
                }
            }

            uint32_t pa0[4][4];
            #pragma unroll
            for (int kst = 0; kst < 4; kst++) {
                pa0[kst][0] = h2ex2(sc0[2*kst  ][0], sc0[2*kst  ][1]);
                pa0[kst][1] = h2ex2(sc0[2*kst  ][2], sc0[2*kst  ][3]);
                pa0[kst][2] = h2ex2(sc0[2*kst+1][0], sc0[2*kst+1][1]);
                pa0[kst][3] = h2ex2(sc0[2*kst+1][2], sc0[2*kst+1][3]);
            }

            float sc1[8][4];
            #pragma unroll
            for (int nt = 0; nt < 8; nt++) {
                sc1[nt][0] = sc1[nt][1] = sc1[nt][2] = sc1[nt][3] = 0.f;
                const __half* kb = &kc[(64 + nt*8 + lrow)*KS_LD + lcol];
                #pragma unroll
                for (int ks2 = 0; ks2 < 2; ks2++) {
                    uint32_t bb[4];
                    ldsm_x4(bb, kb + 32*ks2);
                    mma_f16(sc1[nt], qa[2*ks2],     bb[0], bb[1]);
                    mma_f16(sc1[nt], qa[2*ks2 + 1], bb[2], bb[3]);
                }
            }

            #pragma unroll
            for (int nt = 0; nt < 8; nt++) {
                const __half* vb = &vc[(nt*8 + lrow)*VT_LD + lcol];
                #pragma unroll
                for (int kst2 = 0; kst2 < 2; kst2++) {
                    uint32_t bb[4];
                    ldsm_x4(bb, vb + 32*kst2);
                    mma_f16(oc[nt], pa0[2*kst2],     bb[0], bb[1]);
                    mma_f16(oc[nt], pa0[2*kst2 + 1], bb[2], bb[3]);
                }
            }

            uint32_t pa1[4][4];
            #pragma unroll
            for (int kst = 0; kst < 4; kst++) {
                pa1[kst][0] = h2ex2(sc1[2*kst  ][0], sc1[2*kst  ][1]);
                pa1[kst][1] = h2ex2(sc1[2*kst  ][2], sc1[2*kst  ][3]);
                pa1[kst][2] = h2ex2(sc1[2*kst+1][0], sc1[2*kst+1][1]);
                pa1[kst][3] = h2ex2(sc1[2*kst+1][2], sc1[2*kst+1][3]);
            }

            {
                __half2 a0 = __hadd2(u2h2(pa0[0][0]), u2h2(pa0[0][2]));
                __half2 a1 = __hadd2(u2h2(pa0[1][0]), u2h2(pa0[1][2]));
                __half2 a2 = __hadd2(u2h2(pa0[2][0]), u2h2(pa0[2][2]));
                __half2 a3 = __hadd2(u2h2(pa0[3][0]), u2h2(pa0[3][2]));
                __half2 s0 = __hadd2(__hadd2(a0, a1), __hadd2(a2, a3));
                float2 f0 = __half22float2(s0);
                __half2 b0 = __hadd2(u2h2(pa0[0][1]), u2h2(pa0[0][3]));
                __half2 b1 = __hadd2(u2h2(pa0[1][1]), u2h2(pa0[1][3]));
                __half2 b2 = __hadd2(u2h2(pa0[2][1]), u2h2(pa0[2][3]));
                __half2 b3 = __hadd2(u2h2(pa0[3][1]), u2h2(pa0[3][3]));
                __half2 s1 = __hadd2(__hadd2(b0, b1), __hadd2(b2, b3));
                float2 f1 = __half22float2(s1);
                l0 += f0.x + f0.y;
                l1 += f1.x + f1.y;
            }

            #pragma unroll
            for (int nt = 0; nt < 8; nt++) {
                const __half* vb = &vc[(nt*8 + lrow)*VT_LD + 64 + lcol];
                #pragma unroll
                for (int kst2 = 0; kst2 < 2; kst2++) {
                    uint32_t bb[4];
                    ldsm_x4(bb, vb + 32*kst2);
                    mma_f16(oc[nt], pa1[2*kst2],     bb[0], bb[1]);
                    mma_f16(oc[nt], pa1[2*kst2 + 1], bb[2], bb[3]);
                }
            }

            {
                __half2 a0 = __hadd2(u2h2(pa1[0][0]), u2h2(pa1[0][2]));
                __half2 a1 = __hadd2(u2h2(pa1[1][0]), u2h2(pa1[1][2]));
                __half2 a2 = __hadd2(u2h2(pa1[2][0]), u2h2(pa1[2][2]));
                __half2 a3 = __hadd2(u2h2(pa1[3][0]), u2h2(pa1[3][2]));
                __half2 s0 = __hadd2(__hadd2(a0, a1), __hadd2(a2, a3));
                float2 f0 = __half22float2(s0);
                __half2 b0 = __hadd2(u2h2(pa1[0][1]), u2h2(pa1[0][3]));
                __half2 b1 = __hadd2(u2h2(pa1[1][1]), u2h2(pa1[1][3]));
                __half2 b2 = __hadd2(u2h2(pa1[2][1]), u2h2(pa1[2][3]));
                __half2 b3 = __hadd2(u2h2(pa1[3][1]), u2h2(pa1[3][3]));
                __half2 s1 = __hadd2(__hadd2(b0, b1), __hadd2(b2, b3));
                float2 f1 = __half22float2(s1);
                l0 += f0.x + f0.y;
                l1 += f1.x + f1.y;
            }
        }
        __syncthreads();
    }

    // add stolen partials (each row-tile w has exactly one slot)
    if (act) {
        const float* sp = slots + (size_t)(w*32 + lane)*34;
        #pragma unroll
        for (int nt = 0; nt < 8; nt++)
            #pragma unroll
            for (int j = 0; j < 4; j++) oc[nt][j] += sp[nt*4 + j];
        l0 += sp[32];
        l1 += sp[33];
    }

    l0 += __shfl_xor_sync(0xffffffffu, l0, 1);
    l0 += __shfl_xor_sync(0xffffffffu, l0, 2);
    l1 += __shfl_xor_sync(0xffffffffu, l1, 1);
    l1 += __shfl_xor_sync(0xffffffffu, l1, 2);

    float yacc[8][4];
    #pragma unroll
    for (int nt = 0; nt < 8; nt++)
        yacc[nt][0] = yacc[nt][1] = yacc[nt][2] = yacc[nt][3] = 0.f;

    if (act) {
        float inv0 = 1.f / l0, inv1 = 1.f / l1;

        uint32_t fa[4][4];
        #pragma unroll
        for (int ks = 0; ks < 4; ks++) {
            fa[ks][0] = pack2(oc[2*ks  ][0]*inv0, oc[2*ks  ][1]*inv0);
            fa[ks][1] = pack2(oc[2*ks  ][2]*inv1, oc[2*ks  ][3]*inv1);
            fa[ks][2] = pack2(oc[2*ks+1][0]*inv0, oc[2*ks+1][1]*inv0);
            fa[ks][3] = pack2(oc[2*ks+1][2]*inv1, oc[2*ks+1][3]*inv1);
        }

        for (int ch = 0; ch < 4; ch++) {
            float hacc[8][4];
            #pragma unroll
            for (int nt = 0; nt < 8; nt++) {
                hacc[nt][0] = hacc[nt][1] = hacc[nt][2] = hacc[nt][3] = 0.f;
                const __half* wb = &w1s[(ch*64 + nt*8 + lrow)*W1_LD + lcol];
                #pragma unroll
                for (int ks2 = 0; ks2 < 2; ks2++) {
                    uint32_t bb[4];
                    ldsm_x4(bb, wb + 32*ks2);
                    mma_f16(hacc[nt], fa[2*ks2],     bb[0], bb[1]);
                    mma_f16(hacc[nt], fa[2*ks2 + 1], bb[2], bb[3]);
                }
            }
            #pragma unroll
            for (int nt = 0; nt < 8; nt++)
                #pragma unroll
                for (int j = 0; j < 4; j++) {
                    float v = hacc[nt][j];
                    hacc[nt][j] = 0.5f * v * (1.f + erff(v * 0.70710678118654752f));
                }
            uint32_t ha[4][4];
            #pragma unroll
            for (int kst = 0; kst < 4; kst++) {
                ha[kst][0] = pack2(hacc[2*kst  ][0], hacc[2*kst  ][1]);
                ha[kst][1] = pack2(hacc[2*kst  ][2], hacc[2*kst  ][3]);
                ha[kst][2] = pack2(hacc[2*kst+1][0], hacc[2*kst+1][1]);
                ha[kst][3] = pack2(hacc[2*kst+1][2], hacc[2*kst+1][3]);
            }
            #pragma unroll
            for (int nt = 0; nt < 8; nt++) {
                const __half* wb = &w2s[(nt*8 + lrow)*W2_LD + ch*64 + lcol];
                #pragma unroll
                for (int kst2 = 0; kst2 < 2; kst2++) {
                    uint32_t bb[4];
                    ldsm_x4(bb, wb + 32*kst2);
                    mma_f16(yacc[nt], ha[2*kst2],     bb[0], bb[1]);
                    mma_f16(yacc[nt], ha[2*kst2 + 1], bb[2], bb[3]);
                }
            }
        }
    }
    __syncthreads();   // all K/V smem reads done; reuse base as fp32 buffer

    float* ys = (float*)smem;   // [64 c][YS_LD]
    if (act) {
        #pragma unroll
        for (int nt = 0; nt < 8; nt++) {
            int c0 = nt*8 + 2*t4;
            ys[ c0     *YS_LD + row0    ] = yacc[nt][0];
            ys[(c0 + 1)*YS_LD + row0    ] = yacc[nt][1];
            ys[ c0     *YS_LD + row0 + 8] = yacc[nt][2];
            ys[(c0 + 1)*YS_LD + row0 + 8] = yacc[nt][3];
        }
    }
    __syncthreads();

    for (int idx = t; idx < 64*nq; idx += 256) {
        int c = idx / nq, n = idx - c*nq;
        gY[((b<<6) + c)*Nn + q0 + n] = ys[c*YS_LD + n];
    }
    if (t < 64) {
        int c = t;
        float s = 0.f, s2 = 0.f;
        int n = c;
        for (int j = 0; j < nq; j++) {
            float v = ys[c*YS_LD + n];
            s += v; s2 = fmaf(v, v, s2);
            if (++n == nq) n = 0;
        }
        atomicAdd(&gBNsum[c], s);
        atomicAdd(&gBNsum[64 + c], s2);
    }
}

// ---------------- K3: apply BN + residual (float4, 1024 blocks) ----------------
__global__ void bnapply_kernel(const float* __restrict__ gamma,
                               const float* __restrict__ beta,
                               float* __restrict__ out)
{
    int i4 = blockIdx.x * blockDim.x + threadIdx.x;
    int c = (i4 >> 10) & 63;
    const float invN = 1.f / (Bsz * Nn);
    float mean = gBNsum[c] * invN;
    float var  = gBNsum[64 + c] * invN - mean*mean;
    float is   = rsqrtf(var + EPSBN) * gamma[c];
    float bias = beta[c] - mean * is;
    float4 y = ((const float4*)gY)[i4];
    float4 f = ((const float4*)gFl)[i4];
    float4 o;
    o.x = y.x*is + bias + f.x;
    o.y = y.y*is + bias + f.y;
    o.z = y.z*is + bias + f.z;
    o.w = y.w*is + bias + f.w;
    ((float4*)out)[i4] = o;
}

// ---------------- launch ----------------
extern "C" void kernel_launch(void* const* d_in, const int* in_sizes, int n_in,
                              void* d_out, int out_size)
{
    const float* Fs    = (const float*)d_in[0];
    const float* Ff    = (const float*)d_in[1];
    const float* Wq1   = (const float*)d_in[2];
    const float* Wk1   = (const float*)d_in[3];
    const float* Wq2   = (const float*)d_in[4];
    const float* Wk2   = (const float*)d_in[5];
    const float* Wv    = (const float*)d_in[6];
    const float* Wproj = (const float*)d_in[7];
    const float* W1    = (const float*)d_in[8];
    const float* W2    = (const float*)d_in[9];
    const float* gamma = (const float*)d_in[10];
    const float* beta  = (const float*)d_in[11];
    const float* lam   = (const float*)d_in[12];
    float* out = (float*)d_out;

    prep_kernel<<<192, 256>>>(Wq1, Wk1, Wq2, Wk2, Wv, Wproj, W1, W2, lam);

    size_t proj_smem = (size_t)PROJ_SMEM_HALFS * sizeof(__half);
    cudaFuncSetAttribute(proj_kernel, cudaFuncAttributeMaxDynamicSharedMemorySize, (int)proj_smem);
    proj_kernel<<<dim3(32, Bsz), 256, proj_smem>>>(Fs, Ff);

    cudaFuncSetAttribute(flash_kernel, cudaFuncAttributeMaxDynamicSharedMemorySize, FLASH_SMEM_BYTES);
    flash_kernel<<<dim3(37, Bsz), 256, FLASH_SMEM_BYTES>>>();

    bnapply_kernel<<<(Bsz*Cc*Nn)/1024, 256>>>(gamma, beta, out);
}

// round 17
// speedup vs baseline: 1.1250x; 1.1250x over previous
#include <cuda_runtime.h>
#include <cuda_fp16.h>
#include <math.h>
#include <stdint.h>

// Problem constants
#define Bsz 4
#define Cc  64
#define Nn  4096
#define HIDD 256
#define EPSBN 1e-5f
#define LOG2E 1.44269504088896340736f

// ---------------- scratch (__device__ globals; no allocation) ----------------
__device__ float  gFl [Bsz*Cc*Nn];     // Fs+Ff, channel-major (fp32, exact residual)
__device__ __half gQ  [Bsz*Nn*64];     // q~ = M^T x, token-major
__device__ __half gK  [Bsz*Nn*64];     // k = x, token-major fp16
__device__ __half gVT [Bsz*Cc*Nn];     // v~ = (Wproj Wv) x, out-channel-major
__device__ float  gY  [Bsz*Cc*Nn];     // FFN output, channel-major
__device__ float  gBNsum[2*Cc];        // per-channel sum / sumsq accumulators

// fp16 weight caches (filled by prep kernel each launch)
__device__ __half gMh  [4096];         // folded differential matrix (incl. scale*log2e*lambda)
__device__ __half gWpvh[4096];         // Wpv = Wproj @ Wv, fp16
__device__ __half gW1h [HIDD*Cc];
__device__ __half gW2h [Cc*HIDD];

// ---------------- mma / ldmatrix / math helpers ----------------
__device__ __forceinline__ void mma_f16(float* c, const uint32_t* a, uint32_t b0, uint32_t b1) {
    asm volatile(
        "mma.sync.aligned.m16n8k16.row.col.f32.f16.f16.f32 "
        "{%0,%1,%2,%3}, {%4,%5,%6,%7}, {%8,%9}, {%0,%1,%2,%3};"
        : "+f"(c[0]), "+f"(c[1]), "+f"(c[2]), "+f"(c[3])
        : "r"(a[0]), "r"(a[1]), "r"(a[2]), "r"(a[3]), "r"(b0), "r"(b1));
}
__device__ __forceinline__ void ldsm_x4(uint32_t* r, const __half* p) {
    uint32_t addr = (uint32_t)__cvta_generic_to_shared(p);
    asm volatile("ldmatrix.sync.aligned.m8n8.x4.shared.b16 {%0,%1,%2,%3}, [%4];"
        : "=r"(r[0]), "=r"(r[1]), "=r"(r[2]), "=r"(r[3]) : "r"(addr));
}
__device__ __forceinline__ uint32_t pack2(float x, float y) {
    __half2 h = __floats2half2_rn(x, y);
    return *(uint32_t*)&h;
}
__device__ __forceinline__ uint32_t h2ex2(float x, float y) {
    uint32_t p = pack2(x, y), r;
    asm("ex2.approx.f16x2 %0, %1;" : "=r"(r) : "r"(p));
    return r;
}
__device__ __forceinline__ __half2 u2h2(uint32_t u) { return *(__half2*)&u; }
__device__ __forceinline__ void cp16(void* s, const void* g) {
    uint32_t sa = (uint32_t)__cvta_generic_to_shared(s);
    asm volatile("cp.async.cg.shared.global [%0], [%1], 16;" :: "r"(sa), "l"(g));
}

// ---------------- K0: prep — Meff, Wpv (4-way d-split fp32), W1/W2 fp16, BN zero ----------------
__global__ void __launch_bounds__(256) prep_kernel(
    const float* __restrict__ Wq1, const float* __restrict__ Wk1,
    const float* __restrict__ Wq2, const float* __restrict__ Wk2,
    const float* __restrict__ Wv,  const float* __restrict__ Wproj,
    const float* __restrict__ W1,  const float* __restrict__ W2,
    const float* __restrict__ lam_p)
{
    if (blockIdx.x < 64) {
        __shared__ float red[3][64];
        int j  = blockIdx.x;
        int c  = threadIdx.x & 63;
        int sl = threadIdx.x >> 6;
        float lam = __ldg(lam_p);
        float acc = 0.f;
        #pragma unroll
        for (int i = 0; i < 16; i++) {
            int d = sl*16 + i;
            acc = fmaf(__ldg(&Wk1[d*64 + j]), __ldg(&Wq1[d*64 + c]), acc);
            acc = fmaf(-lam*__ldg(&Wk2[d*64 + j]), __ldg(&Wq2[d*64 + c]), acc);
        }
        if (sl > 0) red[sl - 1][c] = acc;
        __syncthreads();
        if (sl == 0) {
            float s = acc + red[0][c] + red[1][c] + red[2][c];
            gMh[j*64 + c] = __float2half(s * 0.125f * LOG2E);
        }
    } else if (blockIdx.x < 128) {
        __shared__ float red[3][64];
        int j  = blockIdx.x - 64;
        int c  = threadIdx.x & 63;
        int sl = threadIdx.x >> 6;
        float acc = 0.f;
        #pragma unroll
        for (int i = 0; i < 16; i++) {
            int d = sl*16 + i;
            acc = fmaf(__ldg(&Wproj[j*64 + d]), __ldg(&Wv[d*64 + c]), acc);
        }
        if (sl > 0) red[sl - 1][c] = acc;
        __syncthreads();
        if (sl == 0) {
            float s = acc + red[0][c] + red[1][c] + red[2][c];
            gWpvh[j*64 + c] = __float2half(s);
        }
    } else {
        int bb = blockIdx.x - 128;
        if (bb == 0 && threadIdx.x < 128) gBNsum[threadIdx.x] = 0.f;
        int base = bb*512 + threadIdx.x;
        #pragma unroll
        for (int r = 0; r < 2; r++) {
            int i = base + r*256;
            if (i < 16384)       gW1h[i]         = __float2half(__ldg(&W1[i]));
            else                 gW2h[i - 16384] = __float2half(__ldg(&W2[i - 16384]));
        }
    }
}

// ---------------- K1: fused add + q~ / v~ projections + k copy ----------------
#define XS_LD 72
#define WS_LD 72
#define VTS_LD 136
#define PROJ_SMEM_HALFS (128*XS_LD + 128*WS_LD)

__global__ void __launch_bounds__(256) proj_kernel(
    const float* __restrict__ Fs, const float* __restrict__ Ff)
{
    extern __shared__ __half shp[];
    __half* xs = shp;                 // [128 tok][72]; later reused as V transpose
    __half* ws = shp + 128*XS_LD;     // [2*64 rows][72]: Meff then Wpv

    int b  = blockIdx.y;
    int n0 = blockIdx.x << 7;
    int t  = threadIdx.x;
    int w = t >> 5, lane = t & 31, g = lane >> 2, t4 = lane & 3;
    int lrow = lane & 7, lcol = (lane >> 3) * 8;

    for (int idx = t; idx < 8192; idx += 256) {
        int c = idx >> 7, n = idx & 127;
        size_t gi = (size_t)((b<<6) + c)*Nn + n0 + n;
        float v = Fs[gi] + Ff[gi];
        gFl[gi] = v;
        xs[n*XS_LD + c] = __float2half(v);
    }
    for (int idx = t; idx < 512; idx += 256) {
        int r = idx >> 3, ch = idx & 7;
        *(uint4*)&ws[r*WS_LD + ch*8] = ((const uint4*)gMh)[r*8 + ch];
    }
    for (int idx = t; idx < 512; idx += 256) {
        int r = idx >> 3, ch = idx & 7;
        *(uint4*)&ws[(64 + r)*WS_LD + ch*8] = ((const uint4*)gWpvh)[r*8 + ch];
    }
    __syncthreads();

    // k = x: fp16 copy out
    for (int idx = t; idx < 1024; idx += 256) {
        int r = idx >> 3, ch = idx & 7;
        ((uint4*)&gK[(size_t)(b*Nn + n0 + r)*64])[ch] = *(uint4*)&xs[r*XS_LD + ch*8];
    }

    int row0 = w*16 + g;

    uint32_t xa[4][4];
    #pragma unroll
    for (int ks = 0; ks < 4; ks++) {
        xa[ks][0] = *(uint32_t*)&xs[ row0     *XS_LD + 16*ks + 2*t4];
        xa[ks][1] = *(uint32_t*)&xs[(row0 + 8)*XS_LD + 16*ks + 2*t4];
        xa[ks][2] = *(uint32_t*)&xs[ row0     *XS_LD + 16*ks + 2*t4 + 8];
        xa[ks][3] = *(uint32_t*)&xs[(row0 + 8)*XS_LD + 16*ks + 2*t4 + 8];
    }

    for (int m = 0; m < 2; m++) {
        float acc[8][4];
        #pragma unroll
        for (int nt = 0; nt < 8; nt++)
            acc[nt][0] = acc[nt][1] = acc[nt][2] = acc[nt][3] = 0.f;

        #pragma unroll
        for (int nt = 0; nt < 8; nt++) {
            const __half* wb = ws + (m*64 + nt*8 + lrow)*WS_LD + lcol;
            #pragma unroll
            for (int ks2 = 0; ks2 < 2; ks2++) {
                uint32_t bb[4];
                ldsm_x4(bb, wb + 32*ks2);
                mma_f16(acc[nt], xa[2*ks2],     bb[0], bb[1]);
                mma_f16(acc[nt], xa[2*ks2 + 1], bb[2], bb[3]);
            }
        }

        if (m == 1) {
            // V: transpose through smem, then coalesced gVT rows
            __syncthreads();
            __half* vts = xs;              // [64 d][VTS_LD]
            #pragma unroll
            for (int nt = 0; nt < 8; nt++) {
                int d0 = nt*8 + 2*t4;
                vts[ d0     *VTS_LD + row0    ] = __float2half(acc[nt][0]);
                vts[(d0 + 1)*VTS_LD + row0    ] = __float2half(acc[nt][1]);
                vts[ d0     *VTS_LD + row0 + 8] = __float2half(acc[nt][2]);
                vts[(d0 + 1)*VTS_LD + row0 + 8] = __float2half(acc[nt][3]);
            }
            __syncthreads();
            for (int idx = t; idx < 1024; idx += 256) {
                int d = idx >> 4, ch = idx & 15;
                ((uint4*)&gVT[(size_t)((b<<6) + d)*Nn + n0])[ch] = *(uint4*)&vts[d*VTS_LD + ch*8];
            }
        } else {
            #pragma unroll
            for (int nt = 0; nt < 8; nt++) {
                *(uint32_t*)&gQ[(size_t)(b*Nn + n0 + row0    )*64 + nt*8 + 2*t4]
                    = pack2(acc[nt][0], acc[nt][1]);
                *(uint32_t*)&gQ[(size_t)(b*Nn + n0 + row0 + 8)*64 + nt*8 + 2*t4]
                    = pack2(acc[nt][2], acc[nt][3]);
            }
        }
    }
}

// ---------------- K2: flash (triple-buffered, single barrier/iter) + FFN + BN ----------------
#define KTILE 128
#define KS_LD 72
#define VT_LD 136
#define W1_LD 72
#define W2_LD 264
#define QS_LD 72
#define YS_LD 132
#define KBUF_B (KTILE*KS_LD*2)        // 18432
#define VBUF_B (64*VT_LD*2)           // 17408
#define VBASE  (3*KBUF_B)             // 55296
#define W1o (3*KBUF_B + 3*VBUF_B)     // 107520
#define W2o (W1o + HIDD*W1_LD*2)      // 144384
#define FLASH_SMEM_BYTES (W2o + 64*W2_LD*2)   // 178176

__global__ void __launch_bounds__(256) flash_kernel()
{
    extern __shared__ char smem[];
    __half* w1s = (__half*)(smem + W1o);
    __half* w2s = (__half*)(smem + W2o);

    int bx = blockIdx.x;              // 0..36
    int b  = blockIdx.y;
    int nq   = (bx < 34) ? 112 : 96;  // 34*112 + 3*96 = 4096
    int q0   = (bx < 34) ? bx*112 : 3808 + (bx - 34)*96;
    int nwq  = nq >> 4;               // active warps: 7 or 6

    int t  = threadIdx.x;
    int w = t >> 5, lane = t & 31, g = lane >> 2, t4 = lane & 3;
    bool act = (w < nwq);
    int row0 = act ? (w*16 + g) : g;
    int row1 = row0 + 8;
    int lrow = lane & 7, lcol = (lane >> 3) * 8;

    // stage FFN weights
    for (int idx = t; idx < 2048; idx += 256) {
        int e = idx >> 3, ch = idx & 7;
        *(uint4*)&w1s[e*W1_LD + ch*8] = ((const uint4*)gW1h)[e*8 + ch];
    }
    for (int idx = t; idx < 2048; idx += 256) {
        int c = idx >> 5, ch = idx & 31;
        *(uint4*)&w2s[c*W2_LD + ch*8] = ((const uint4*)gW2h)[c*32 + ch];
    }
    // stage Q tile at smem base (inside K buffer 0; consumed before prefetch)
    __half* qs = (__half*)smem;
    const uint4* Qg = (const uint4*)(gQ + (size_t)(b*Nn + q0)*64);
    for (int idx = t; idx < nq*8; idx += 256) {
        int r = idx >> 3, ch = idx & 7;
        *(uint4*)&qs[r*QS_LD + ch*8] = Qg[r*8 + ch];
    }
    __syncthreads();

    uint32_t qa[4][4];
    #pragma unroll
    for (int ks = 0; ks < 4; ks++) {
        qa[ks][0] = *(uint32_t*)&qs[row0*QS_LD + 16*ks + 2*t4];
        qa[ks][1] = *(uint32_t*)&qs[row1*QS_LD + 16*ks + 2*t4];
        qa[ks][2] = *(uint32_t*)&qs[row0*QS_LD + 16*ks + 2*t4 + 8];
        qa[ks][3] = *(uint32_t*)&qs[row1*QS_LD + 16*ks + 2*t4 + 8];
    }
    __syncthreads();   // qs consumed; K buffers free

    float oc[8][4];
    #pragma unroll
    for (int nt = 0; nt < 8; nt++)
        oc[nt][0] = oc[nt][1] = oc[nt][2] = oc[nt][3] = 0.f;
    float l0 = 0.f, l1 = 0.f;

    const uint4* Kg = (const uint4*)(gK  + (size_t)b*Nn*64);
    const uint4* Vg = (const uint4*)(gVT + (size_t)b*64*Nn);

    {   // prefetch tile 0 into buffer 0
        __half* kd = (__half*)(smem);
        __half* vd = (__half*)(smem + VBASE);
        for (int idx = t; idx < 1024; idx += 256) {
            int r = idx >> 3, ch = idx & 7;
            cp16(&kd[r*KS_LD + ch*8], &Kg[r*8 + ch]);
        }
        for (int idx = t; idx < 1024; idx += 256) {
            int d = idx >> 4, ch = idx & 15;
            cp16(&vd[d*VT_LD + ch*8], &Vg[d*512 + ch]);
        }
        asm volatile("cp.async.commit_group;");
    }

    int bufc = 0;
    for (int kt = 0; kt < Nn/KTILE; kt++) {
        __half* kc = (__half*)(smem + bufc*KBUF_B);
        __half* vc = (__half*)(smem + VBASE + bufc*VBUF_B);
        int bufn = (bufc == 2) ? 0 : bufc + 1;

        if (kt + 1 < Nn/KTILE) {
            __half* kd = (__half*)(smem + bufn*KBUF_B);
            __half* vd = (__half*)(smem + VBASE + bufn*VBUF_B);
            int kt0 = (kt + 1) * KTILE;
            for (int idx = t; idx < 1024; idx += 256) {
                int r = idx >> 3, ch = idx & 7;
                cp16(&kd[r*KS_LD + ch*8], &Kg[(kt0 + r)*8 + ch]);
            }
            for (int idx = t; idx < 1024; idx += 256) {
                int d = idx >> 4, ch = idx & 15;
                cp16(&vd[d*VT_LD + ch*8], &Vg[d*512 + (kt0 >> 3) + ch]);
            }
            asm volatile("cp.async.commit_group;");
            asm volatile("cp.async.wait_group 1;");
        } else {
            asm volatile("cp.async.wait_group 0;");
        }
        __syncthreads();   // single barrier per iteration (triple buffer makes tail barrier unneeded)
        bufc = bufn;

        if (act) {
            // pipelined halves
            float sc0[8][4];
            #pragma unroll
            for (int nt = 0; nt < 8; nt++) {
                sc0[nt][0] = sc0[nt][1] = sc0[nt][2] = sc0[nt][3] = 0.f;
                const __half* kb = &kc[(nt*8 + lrow)*KS_LD + lcol];
                #pragma unroll
                for (int ks2 = 0; ks2 < 2; ks2++) {
                    uint32_t bb[4];
                    ldsm_x4(bb, kb + 32*ks2);
                    mma_f16(sc0[nt], qa[2*ks2],     bb[0], bb[1]);
                    mma_f16(sc0[nt], qa[2*ks2 + 1], bb[2], bb[3]);
                }
            }

            uint32_t pa0[4][4];
            #pragma unroll
            for (int kst = 0; kst < 4; kst++) {
                pa0[kst][0] = h2ex2(sc0[2*kst  ][0], sc0[2*kst  ][1]);
                pa0[kst][1] = h2ex2(sc0[2*kst  ][2], sc0[2*kst  ][3]);
                pa0[kst][2] = h2ex2(sc0[2*kst+1][0], sc0[2*kst+1][1]);
                pa0[kst][3] = h2ex2(sc0[2*kst+1][2], sc0[2*kst+1][3]);
            }

            float sc1[8][4];
            #pragma unroll
            for (int nt = 0; nt < 8; nt++) {
                sc1[nt][0] = sc1[nt][1] = sc1[nt][2] = sc1[nt][3] = 0.f;
                const __half* kb = &kc[(64 + nt*8 + lrow)*KS_LD + lcol];
                #pragma unroll
                for (int ks2 = 0; ks2 < 2; ks2++) {
                    uint32_t bb[4];
                    ldsm_x4(bb, kb + 32*ks2);
                    mma_f16(sc1[nt], qa[2*ks2],     bb[0], bb[1]);
                    mma_f16(sc1[nt], qa[2*ks2 + 1], bb[2], bb[3]);
                }
            }

            // PV half 0
            #pragma unroll
            for (int nt = 0; nt < 8; nt++) {
                const __half* vb = &vc[(nt*8 + lrow)*VT_LD + lcol];
                #pragma unroll
                for (int kst2 = 0; kst2 < 2; kst2++) {
                    uint32_t bb[4];
                    ldsm_x4(bb, vb + 32*kst2);
                    mma_f16(oc[nt], pa0[2*kst2],     bb[0], bb[1]);
                    mma_f16(oc[nt], pa0[2*kst2 + 1], bb[2], bb[3]);
                }
            }

            uint32_t pa1[4][4];
            #pragma unroll
            for (int kst = 0; kst < 4; kst++) {
                pa1[kst][0] = h2ex2(sc1[2*kst  ][0], sc1[2*kst  ][1]);
                pa1[kst][1] = h2ex2(sc1[2*kst  ][2], sc1[2*kst  ][3]);
                pa1[kst][2] = h2ex2(sc1[2*kst+1][0], sc1[2*kst+1][1]);
                pa1[kst][3] = h2ex2(sc1[2*kst+1][2], sc1[2*kst+1][3]);
            }

            {
                __half2 a0 = __hadd2(u2h2(pa0[0][0]), u2h2(pa0[0][2]));
                __half2 a1 = __hadd2(u2h2(pa0[1][0]), u2h2(pa0[1][2]));
                __half2 a2 = __hadd2(u2h2(pa0[2][0]), u2h2(pa0[2][2]));
                __half2 a3 = __hadd2(u2h2(pa0[3][0]), u2h2(pa0[3][2]));
                __half2 s0 = __hadd2(__hadd2(a0, a1), __hadd2(a2, a3));
                float2 f0 = __half22float2(s0);
                __half2 b0 = __hadd2(u2h2(pa0[0][1]), u2h2(pa0[0][3]));
                __half2 b1 = __hadd2(u2h2(pa0[1][1]), u2h2(pa0[1][3]));
                __half2 b2 = __hadd2(u2h2(pa0[2][1]), u2h2(pa0[2][3]));
                __half2 b3 = __hadd2(u2h2(pa0[3][1]), u2h2(pa0[3][3]));
                __half2 s1 = __hadd2(__hadd2(b0, b1), __hadd2(b2, b3));
                float2 f1 = __half22float2(s1);
                l0 += f0.x + f0.y;
                l1 += f1.x + f1.y;
            }

            // PV half 1
            #pragma unroll
            for (int nt = 0; nt < 8; nt++) {
                const __half* vb = &vc[(nt*8 + lrow)*VT_LD + 64 + lcol];
                #pragma unroll
                for (int kst2 = 0; kst2 < 2; kst2++) {
                    uint32_t bb[4];
                    ldsm_x4(bb, vb + 32*kst2);
                    mma_f16(oc[nt], pa1[2*kst2],     bb[0], bb[1]);
                    mma_f16(oc[nt], pa1[2*kst2 + 1], bb[2], bb[3]);
                }
            }

            {
                __half2 a0 = __hadd2(u2h2(pa1[0][0]), u2h2(pa1[0][2]));
                __half2 a1 = __hadd2(u2h2(pa1[1][0]), u2h2(pa1[1][2]));
                __half2 a2 = __hadd2(u2h2(pa1[2][0]), u2h2(pa1[2][2]));
                __half2 a3 = __hadd2(u2h2(pa1[3][0]), u2h2(pa1[3][2]));
                __half2 s0 = __hadd2(__hadd2(a0, a1), __hadd2(a2, a3));
                float2 f0 = __half22float2(s0);
                __half2 b0 = __hadd2(u2h2(pa1[0][1]), u2h2(pa1[0][3]));
                __half2 b1 = __hadd2(u2h2(pa1[1][1]), u2h2(pa1[1][3]));
                __half2 b2 = __hadd2(u2h2(pa1[2][1]), u2h2(pa1[2][3]));
                __half2 b3 = __hadd2(u2h2(pa1[3][1]), u2h2(pa1[3][3]));
                __half2 s1 = __hadd2(__hadd2(b0, b1), __hadd2(b2, b3));
                float2 f1 = __half22float2(s1);
                l0 += f0.x + f0.y;
                l1 += f1.x + f1.y;
            }
        }
        // no tail barrier: next prefetch targets buffer (kt+2)%3, never a buffer
        // readable by a warp that is at most one top-barrier behind.
    }

    l0 += __shfl_xor_sync(0xffffffffu, l0, 1);
    l0 += __shfl_xor_sync(0xffffffffu, l0, 2);
    l1 += __shfl_xor_sync(0xffffffffu, l1, 1);
    l1 += __shfl_xor_sync(0xffffffffu, l1, 2);

    float yacc[8][4];
    #pragma unroll
    for (int nt = 0; nt < 8; nt++)
        yacc[nt][0] = yacc[nt][1] = yacc[nt][2] = yacc[nt][3] = 0.f;

    if (act) {
        float inv0 = 1.f / l0, inv1 = 1.f / l1;

        uint32_t fa[4][4];
        #pragma unroll
        for (int ks = 0; ks < 4; ks++) {
            fa[ks][0] = pack2(oc[2*ks  ][0]*inv0, oc[2*ks  ][1]*inv0);
            fa[ks][1] = pack2(oc[2*ks  ][2]*inv1, oc[2*ks  ][3]*inv1);
            fa[ks][2] = pack2(oc[2*ks+1][0]*inv0, oc[2*ks+1][1]*inv0);
            fa[ks][3] = pack2(oc[2*ks+1][2]*inv1, oc[2*ks+1][3]*inv1);
        }

        for (int ch = 0; ch < 4; ch++) {
            float hacc[8][4];
            #pragma unroll
            for (int nt = 0; nt < 8; nt++) {
                hacc[nt][0] = hacc[nt][1] = hacc[nt][2] = hacc[nt][3] = 0.f;
                const __half* wb = &w1s[(ch*64 + nt*8 + lrow)*W1_LD + lcol];
                #pragma unroll
                for (int ks2 = 0; ks2 < 2; ks2++) {
                    uint32_t bb[4];
                    ldsm_x4(bb, wb + 32*ks2);
                    mma_f16(hacc[nt], fa[2*ks2],     bb[0], bb[1]);
                    mma_f16(hacc[nt], fa[2*ks2 + 1], bb[2], bb[3]);
                }
            }
            #pragma unroll
            for (int nt = 0; nt < 8; nt++)
                #pragma unroll
                for (int j = 0; j < 4; j++) {
                    float v = hacc[nt][j];
                    hacc[nt][j] = 0.5f * v * (1.f + erff(v * 0.70710678118654752f));
                }
            uint32_t ha[4][4];
            #pragma unroll
            for (int kst = 0; kst < 4; kst++) {
                ha[kst][0] = pack2(hacc[2*kst  ][0], hacc[2*kst  ][1]);
                ha[kst][1] = pack2(hacc[2*kst  ][2], hacc[2*kst  ][3]);
                ha[kst][2] = pack2(hacc[2*kst+1][0], hacc[2*kst+1][1]);
                ha[kst][3] = pack2(hacc[2*kst+1][2], hacc[2*kst+1][3]);
            }
            #pragma unroll
            for (int nt = 0; nt < 8; nt++) {
                const __half* wb = &w2s[(nt*8 + lrow)*W2_LD + ch*64 + lcol];
                #pragma unroll
                for (int kst2 = 0; kst2 < 2; kst2++) {
                    uint32_t bb[4];
                    ldsm_x4(bb, wb + 32*kst2);
                    mma_f16(yacc[nt], ha[2*kst2],     bb[0], bb[1]);
                    mma_f16(yacc[nt], ha[2*kst2 + 1], bb[2], bb[3]);
                }
            }
        }
    }
    __syncthreads();   // all K/V smem reads done; reuse base as fp32 buffer

    float* ys = (float*)smem;   // [64 c][YS_LD], columns 0..nq-1 valid
    if (act) {
        #pragma unroll
        for (int nt = 0; nt < 8; nt++) {
            int c0 = nt*8 + 2*t4;
            ys[ c0     *YS_LD + row0    ] = yacc[nt][0];
            ys[(c0 + 1)*YS_LD + row0    ] = yacc[nt][1];
            ys[ c0     *YS_LD + row0 + 8] = yacc[nt][2];
            ys[(c0 + 1)*YS_LD + row0 + 8] = yacc[nt][3];
        }
    }
    __syncthreads();

    for (int idx = t; idx < 64*nq; idx += 256) {
        int c = idx / nq, n = idx - c*nq;
        gY[((b<<6) + c)*Nn + q0 + n] = ys[c*YS_LD + n];
    }
    if (t < 64) {
        int c = t;
        float s = 0.f, s2 = 0.f;
        int n = c;
        for (int j = 0; j < nq; j++) {
            float v = ys[c*YS_LD + n];
            s += v; s2 = fmaf(v, v, s2);
            if (++n == nq) n = 0;
        }
        atomicAdd(&gBNsum[c], s);
        atomicAdd(&gBNsum[64 + c], s2);
    }
}

// ---------------- K3: apply BN + residual (float4, 1024 blocks) ----------------
__global__ void bnapply_kernel(const float* __restrict__ gamma,
                               const float* __restrict__ beta,
                               float* __restrict__ out)
{
    int i4 = blockIdx.x * blockDim.x + threadIdx.x;
    int c = (i4 >> 10) & 63;
    const float invN = 1.f / (Bsz * Nn);
    float mean = gBNsum[c] * invN;
    float var  = gBNsum[64 + c] * invN - mean*mean;
    float is   = rsqrtf(var + EPSBN) * gamma[c];
    float bias = beta[c] - mean * is;
    float4 y = ((const float4*)gY)[i4];
    float4 f = ((const float4*)gFl)[i4];
    float4 o;
    o.x = y.x*is + bias + f.x;
    o.y = y.y*is + bias + f.y;
    o.z = y.z*is + bias + f.z;
    o.w = y.w*is + bias + f.w;
    ((float4*)out)[i4] = o;
}

// ---------------- launch ----------------
extern "C" void kernel_launch(void* const* d_in, const int* in_sizes, int n_in,
                              void* d_out, int out_size)
{
    const float* Fs    = (const float*)d_in[0];
    const float* Ff    = (const float*)d_in[1];
    const float* Wq1   = (const float*)d_in[2];
    const float* Wk1   = (const float*)d_in[3];
    const float* Wq2   = (const float*)d_in[4];
    const float* Wk2   = (const float*)d_in[5];
    const float* Wv    = (const float*)d_in[6];
    const float* Wproj = (const float*)d_in[7];
    const float* W1    = (const float*)d_in[8];
    const float* W2    = (const float*)d_in[9];
    const float* gamma = (const float*)d_in[10];
    const float* beta  = (const float*)d_in[11];
    const float* lam   = (const float*)d_in[12];
    float* out = (float*)d_out;

    prep_kernel<<<192, 256>>>(Wq1, Wk1, Wq2, Wk2, Wv, Wproj, W1, W2, lam);

    size_t proj_smem = (size_t)PROJ_SMEM_HALFS * sizeof(__half);
    cudaFuncSetAttribute(proj_kernel, cudaFuncAttributeMaxDynamicSharedMemorySize, (int)proj_smem);
    proj_kernel<<<dim3(32, Bsz), 256, proj_smem>>>(Fs, Ff);

    cudaFuncSetAttribute(flash_kernel, cudaFuncAttributeMaxDynamicSharedMemorySize, FLASH_SMEM_BYTES);
    flash_kernel<<<dim3(37, Bsz), 256, FLASH_SMEM_BYTES>>>();

    bnapply_kernel<<<(Bsz*Cc*Nn)/1024, 256>>>(gamma, beta, out);
}